// round 1
// baseline (speedup 1.0000x reference)
#include <cuda_runtime.h>

#define BB 2
#define TT 1024
#define EE 1024
#define HH 16
#define HD 64
#define NTOK (BB*TT)      // 2048
#define NBH  (BB*HH)      // 32
#define ALPHA 0.25f       // (1/sqrt(HD)) / TEMP = 0.125 * 2

// ---------------- device scratch (no allocation allowed) ----------------
// projections: 0=Q,1=Q2,2=Q3,3=K,4=V   each [NTOK, EE]
__device__ float  g_P[5][(size_t)NTOK * EE];
__device__ float  g_E2[(size_t)NBH * TT * TT];   // exp scores tensor 2
__device__ float  g_E3[(size_t)NBH * TT * TT];   // exp scores tensor 3
__device__ float  g_AO[(size_t)NTOK * EE];       // attention output pre-projection
__device__ double g_sums[3 * NBH];               // global softmax denominators

// ---------------- zero the softmax sums (must run each replay) ----------
__global__ void k_zero_sums() {
    int i = threadIdx.x;
    if (i < 3 * NBH) g_sums[i] = 0.0;
}

// ---------------- generic 128x128x16 NT GEMM + bias ---------------------
// C[M,N] = A[M,K] * W[N,K]^T + bias[N]
// grid: (N/128, M/128), block: 256 threads, 8x8 per thread
__global__ __launch_bounds__(256) void k_gemm_bias(
    const float* __restrict__ A, const float* __restrict__ W,
    const float* __restrict__ bias, float* __restrict__ C,
    int K, int lda, int ldb, int ldc)
{
    __shared__ float As[16][129];
    __shared__ float Bs[16][129];
    const int tid = threadIdx.x;
    const int tx = tid & 15, ty = tid >> 4;
    const int m0 = blockIdx.y * 128, n0 = blockIdx.x * 128;

    float acc[8][8] = {};
    for (int k0 = 0; k0 < K; k0 += 16) {
#pragma unroll
        for (int e = 0; e < 8; e++) {
            int lin = tid + e * 256;          // 0..2047
            int r = lin >> 4, kk = lin & 15;
            As[kk][r] = A[(size_t)(m0 + r) * lda + k0 + kk];
            Bs[kk][r] = W[(size_t)(n0 + r) * ldb + k0 + kk];
        }
        __syncthreads();
#pragma unroll
        for (int kk = 0; kk < 16; kk++) {
            float a[8], b[8];
#pragma unroll
            for (int i = 0; i < 8; i++) a[i] = As[kk][ty + 16 * i];
#pragma unroll
            for (int j = 0; j < 8; j++) b[j] = Bs[kk][tx + 16 * j];
#pragma unroll
            for (int i = 0; i < 8; i++)
#pragma unroll
                for (int j = 0; j < 8; j++)
                    acc[i][j] = fmaf(a[i], b[j], acc[i][j]);
        }
        __syncthreads();
    }
#pragma unroll
    for (int i = 0; i < 8; i++) {
        int row = m0 + ty + 16 * i;
#pragma unroll
        for (int j = 0; j < 8; j++) {
            int col = n0 + tx + 16 * j;
            C[(size_t)row * ldc + col] = acc[i][j] + bias[col];
        }
    }
}

// ---------------- scores: exp((Qh Kh^T) * ALPHA), fused global sum ------
// grid: (8, 8, 96)  z = tensor*32 + bh ; block 256, 8x8/thread, K=64
__global__ __launch_bounds__(256) void k_score(float* __restrict__ E1out)
{
    __shared__ float As[16][129];
    __shared__ float Bs[16][129];
    __shared__ float red[256];

    const int zz = blockIdx.z;
    const int tensor = zz >> 5;          // 0,1,2
    const int bh = zz & 31;
    const int b = bh >> 4, h = bh & 15;

    const float* Aq = g_P[tensor] + (size_t)b * TT * EE + h * HD;
    const float* Bk = g_P[3]      + (size_t)b * TT * EE + h * HD;
    float* Eo = (tensor == 0) ? E1out : (tensor == 1 ? g_E2 : g_E3);
    Eo += (size_t)bh * TT * TT;

    const int tid = threadIdx.x;
    const int tx = tid & 15, ty = tid >> 4;
    const int m0 = blockIdx.y * 128, n0 = blockIdx.x * 128;

    float acc[8][8] = {};
#pragma unroll
    for (int k0 = 0; k0 < 64; k0 += 16) {
#pragma unroll
        for (int e = 0; e < 8; e++) {
            int lin = tid + e * 256;
            int r = lin >> 4, kk = lin & 15;
            As[kk][r] = Aq[(size_t)(m0 + r) * EE + k0 + kk];
            Bs[kk][r] = Bk[(size_t)(n0 + r) * EE + k0 + kk];
        }
        __syncthreads();
#pragma unroll
        for (int kk = 0; kk < 16; kk++) {
            float a[8], bb[8];
#pragma unroll
            for (int i = 0; i < 8; i++) a[i] = As[kk][ty + 16 * i];
#pragma unroll
            for (int j = 0; j < 8; j++) bb[j] = Bs[kk][tx + 16 * j];
#pragma unroll
            for (int i = 0; i < 8; i++)
#pragma unroll
                for (int j = 0; j < 8; j++)
                    acc[i][j] = fmaf(a[i], bb[j], acc[i][j]);
        }
        __syncthreads();
    }

    float lsum = 0.f;
#pragma unroll
    for (int i = 0; i < 8; i++) {
        int row = m0 + ty + 16 * i;
#pragma unroll
        for (int j = 0; j < 8; j++) {
            int col = n0 + tx + 16 * j;
            float v = __expf(acc[i][j] * ALPHA);
            Eo[(size_t)row * TT + col] = v;
            lsum += v;
        }
    }
    // block reduction, one double atomic per block
    red[tid] = lsum;
    __syncthreads();
    for (int s = 128; s > 0; s >>= 1) {
        if (tid < s) red[tid] += red[tid + s];
        __syncthreads();
    }
    if (tid == 0) atomicAdd(&g_sums[zz], (double)red[0]);
}

// ---------------- AV: attn_out = ((a1+a2+a3)/3) @ V, fused a1 writeback -
// grid: (16 t-tiles, 32 bh), block 256, 4x4/thread, TM=64 TN=64 TK=32
__global__ __launch_bounds__(256) void k_av(float* __restrict__ E1)
{
    __shared__ float Ws[32][65];
    __shared__ float Vs[32][65];

    const int bh = blockIdx.y;
    const int b = bh >> 4, h = bh & 15;
    const int t0 = blockIdx.x * 64;

    const float c1 = (float)((double)TT / g_sums[bh]);
    const float c2 = (float)((double)TT / g_sums[32 + bh]);
    const float c3 = (float)((double)TT / g_sums[64 + bh]);
    const float third = 1.0f / 3.0f;

    float* E1p = E1 + (size_t)bh * TT * TT;
    const float* E2p = g_E2 + (size_t)bh * TT * TT;
    const float* E3p = g_E3 + (size_t)bh * TT * TT;
    const float* Vp  = g_P[4] + (size_t)b * TT * EE + h * HD;

    const int tid = threadIdx.x;
    const int tx = tid & 15, ty = tid >> 4;

    float acc[4][4] = {};
    for (int s0 = 0; s0 < TT; s0 += 32) {
#pragma unroll
        for (int e = 0; e < 8; e++) {
            int lin = tid + e * 256;              // 0..2047
            // weight tile: 64 t x 32 s
            int t_l = lin >> 5, s_l = lin & 31;
            size_t ei = (size_t)(t0 + t_l) * TT + s0 + s_l;
            float e1 = E1p[ei];
            float e2 = E2p[ei];
            float e3 = E3p[ei];
            float a1v = e1 * c1;
            E1p[ei] = a1v;                        // scaled a1 -> d_out (in place)
            Ws[s_l][t_l] = (a1v + e2 * c2 + e3 * c3) * third;
            // V tile: 32 s x 64 d
            int s_v = lin >> 6, d_v = lin & 63;
            Vs[s_v][d_v] = Vp[(size_t)(s0 + s_v) * EE + d_v];
        }
        __syncthreads();
#pragma unroll
        for (int kk = 0; kk < 32; kk++) {
            float a[4], bb[4];
#pragma unroll
            for (int i = 0; i < 4; i++) a[i] = Ws[kk][ty + 16 * i];
#pragma unroll
            for (int j = 0; j < 4; j++) bb[j] = Vs[kk][tx + 16 * j];
#pragma unroll
            for (int i = 0; i < 4; i++)
#pragma unroll
                for (int j = 0; j < 4; j++)
                    acc[i][j] = fmaf(a[i], bb[j], acc[i][j]);
        }
        __syncthreads();
    }
#pragma unroll
    for (int i = 0; i < 4; i++) {
        int trow = t0 + ty + 16 * i;
#pragma unroll
        for (int j = 0; j < 4; j++) {
            g_AO[(size_t)(b * TT + trow) * EE + h * HD + tx + 16 * j] = acc[i][j];
        }
    }
}

// ---------------- launch ------------------------------------------------
extern "C" void kernel_launch(void* const* d_in, const int* in_sizes, int n_in,
                              void* d_out, int out_size)
{
    const float* q1  = (const float*)d_in[0];
    const float* q2  = (const float*)d_in[1];
    const float* key = (const float*)d_in[2];
    const float* val = (const float*)d_in[3];
    const float* Wq  = (const float*)d_in[4];
    const float* bq  = (const float*)d_in[5];
    const float* Wq2 = (const float*)d_in[6];
    const float* bq2 = (const float*)d_in[7];
    const float* Wq3 = (const float*)d_in[8];
    const float* bq3 = (const float*)d_in[9];
    const float* Wk  = (const float*)d_in[10];
    const float* bk  = (const float*)d_in[11];
    const float* Wv  = (const float*)d_in[12];
    const float* bv  = (const float*)d_in[13];
    const float* Wo  = (const float*)d_in[14];
    const float* bo  = (const float*)d_in[15];

    float* out = (float*)d_out;                      // [B,T,E]
    float* a1  = out + (size_t)BB * TT * EE;         // [B,H,T,T]

    float* gP;  cudaGetSymbolAddress((void**)&gP, g_P);
    float* gAO; cudaGetSymbolAddress((void**)&gAO, g_AO);

    k_zero_sums<<<1, 128>>>();

    dim3 blk(256);
    dim3 gproj(EE / 128, NTOK / 128);                // (8, 16)

    // projections: q=q1@Wq^T, q2=q2@Wq2^T, q3=key@Wq3^T, k=key@Wk^T, v=val@Wv^T
    const float* Xs[5] = { q1, q2, key, key, val };
    const float* Wsrc[5] = { Wq, Wq2, Wq3, Wk, Wv };
    const float* bs[5] = { bq, bq2, bq3, bk, bv };
    for (int p = 0; p < 5; p++) {
        k_gemm_bias<<<gproj, blk>>>(Xs[p], Wsrc[p], bs[p],
                                    gP + (size_t)p * NTOK * EE,
                                    EE, EE, EE, EE);
    }

    dim3 gscore(TT / 128, TT / 128, 3 * NBH);        // (8, 8, 96)
    k_score<<<gscore, blk>>>(a1);

    dim3 gav(TT / 64, NBH);                          // (16, 32)
    k_av<<<gav, blk>>>(a1);

    dim3 gout(EE / 128, NTOK / 128);                 // (8, 16)
    k_gemm_bias<<<gout, blk>>>(gAO, Wo, bo, out, EE, EE, EE, EE);
}